// round 6
// baseline (speedup 1.0000x reference)
#include <cuda_runtime.h>
#include <mma.h>

using namespace nvcuda;

#define N_NODES 512
#define SEQ     256
#define C_IN    32
#define B_SZ    8
#define C_OUT   64
#define GDEP    3
#define BETA    0.05f

#define SLICE   (N_NODES * SEQ)              // 131072 floats per (b,c) slice
#define SLOT    (B_SZ * C_IN * SLICE)        // 33554432 floats per hop slot

// Scratch: normalized adjacency + 3 hop buffers (hop1..hop3). hop0 == X read directly.
__device__ float g_An[N_NODES * N_NODES];
__device__ float g_hops[(size_t)GDEP * SLOT];   // 402 MB static device scratch

// ---------------------------------------------------------------------------
// Kernel 1: A' = row-normalize(A + I)
// ---------------------------------------------------------------------------
__global__ void norm_kernel(const float* __restrict__ A) {
    int v = blockIdx.x;
    int tid = threadIdx.x;
    __shared__ float red[256];
    float s = 0.0f;
    for (int w = tid; w < N_NODES; w += 256) {
        float a = A[(size_t)v * N_NODES + w] + (w == v ? 1.0f : 0.0f);
        s += a;
    }
    red[tid] = s;
    __syncthreads();
    for (int off = 128; off > 0; off >>= 1) {
        if (tid < off) red[tid] += red[tid + off];
        __syncthreads();
    }
    float inv = 1.0f / red[0];
    for (int w = tid; w < N_NODES; w += 256) {
        float a = A[(size_t)v * N_NODES + w] + (w == v ? 1.0f : 0.0f);
        g_An[(size_t)v * N_NODES + w] = a * inv;
    }
}

// ---------------------------------------------------------------------------
// Kernel 2: hop GEMM.  For each (b,c) slice: Hk = A'(512x512) @ Hprev(512x256)
// then Hnext = BETA*X + (1-BETA)*Hk.  tf32 WMMA, fp32 accumulate.
// CTA tile: 128 (rows v) x 64 (cols l).  8 warps, warp tile 32x32, frags 2x2.
// grid: (16 tiles, 256 slices), 256 threads.
// ---------------------------------------------------------------------------
__global__ void hop_kernel(const float* __restrict__ X, int src_slot, int dst_slot) {
    const float* __restrict__ src = (src_slot < 0) ? X : (g_hops + (size_t)src_slot * SLOT);
    float* __restrict__ dst = g_hops + (size_t)dst_slot * SLOT;

    const int bc = blockIdx.y;
    const int mt = blockIdx.x & 3;       // 4 row tiles of 128
    const int nt = blockIdx.x >> 2;      // 4 col tiles of 64
    const size_t sbase = (size_t)bc * SLICE;
    const int v0 = mt * 128;
    const int l0 = nt * 64;

    __shared__ __align__(16) float smem[8704];     // 34.8 KB
    float* As = smem;            // [128][36]
    float* Bs = smem + 4608;     // [32][68]

    const int tid = threadIdx.x;
    const int wid = tid >> 5;
    const int warp_m = wid & 3;          // 4 warps along rows (32 each)
    const int warp_n = wid >> 2;         // 2 warps along cols (32 each)

    wmma::fragment<wmma::accumulator, 16, 16, 8, float> acc[2][2];
#pragma unroll
    for (int i = 0; i < 2; i++)
#pragma unroll
        for (int j = 0; j < 2; j++)
            wmma::fill_fragment(acc[i][j], 0.0f);

    for (int k0 = 0; k0 < N_NODES; k0 += 32) {
        // Load A' tile: rows v0..+127, cols k0..+31  (4096 floats)
#pragma unroll
        for (int p = 0; p < 4; p++) {
            int r = p * 32 + (tid >> 3);
            int c = (tid & 7) * 4;
            float4 v = *(const float4*)(g_An + (size_t)(v0 + r) * N_NODES + k0 + c);
            v.x = wmma::__float_to_tf32(v.x);
            v.y = wmma::__float_to_tf32(v.y);
            v.z = wmma::__float_to_tf32(v.z);
            v.w = wmma::__float_to_tf32(v.w);
            *(float4*)(As + r * 36 + c) = v;
        }
        // Load H tile: rows k0..+31, cols l0..+63  (2048 floats)
#pragma unroll
        for (int p = 0; p < 2; p++) {
            int r = p * 16 + (tid >> 4);
            int c = (tid & 15) * 4;
            float4 v = *(const float4*)(src + sbase + (size_t)(k0 + r) * SEQ + l0 + c);
            v.x = wmma::__float_to_tf32(v.x);
            v.y = wmma::__float_to_tf32(v.y);
            v.z = wmma::__float_to_tf32(v.z);
            v.w = wmma::__float_to_tf32(v.w);
            *(float4*)(Bs + r * 68 + c) = v;
        }
        __syncthreads();

#pragma unroll
        for (int ks = 0; ks < 32; ks += 8) {
            wmma::fragment<wmma::matrix_a, 16, 16, 8, wmma::precision::tf32, wmma::row_major> a[2];
            wmma::fragment<wmma::matrix_b, 16, 16, 8, wmma::precision::tf32, wmma::row_major> b[2];
#pragma unroll
            for (int mi = 0; mi < 2; mi++)
                wmma::load_matrix_sync(a[mi], As + (warp_m * 32 + mi * 16) * 36 + ks, 36);
#pragma unroll
            for (int ni = 0; ni < 2; ni++)
                wmma::load_matrix_sync(b[ni], Bs + ks * 68 + warp_n * 32 + ni * 16, 68);
#pragma unroll
            for (int mi = 0; mi < 2; mi++)
#pragma unroll
                for (int ni = 0; ni < 2; ni++)
                    wmma::mma_sync(acc[mi][ni], a[mi], b[ni], acc[mi][ni]);
        }
        __syncthreads();
    }

    // Epilogue: Hnext = BETA*X + (1-BETA)*acc
    float* Cs = smem;  // [128][68] reuse
#pragma unroll
    for (int mi = 0; mi < 2; mi++)
#pragma unroll
        for (int ni = 0; ni < 2; ni++)
            wmma::store_matrix_sync(Cs + (warp_m * 32 + mi * 16) * 68 + warp_n * 32 + ni * 16,
                                    acc[mi][ni], 68, wmma::mem_row_major);
    __syncthreads();

#pragma unroll
    for (int p = 0; p < 8; p++) {
        int r = p * 16 + (tid >> 4);
        int c = (tid & 15) * 4;
        float4 cv = *(const float4*)(Cs + r * 68 + c);
        float4 xv = *(const float4*)(X + sbase + (size_t)(v0 + r) * SEQ + l0 + c);
        float4 h;
        h.x = BETA * xv.x + (1.0f - BETA) * cv.x;
        h.y = BETA * xv.y + (1.0f - BETA) * cv.y;
        h.z = BETA * xv.z + (1.0f - BETA) * cv.z;
        h.w = BETA * xv.w + (1.0f - BETA) * cv.w;
        *(float4*)(dst + sbase + (size_t)(v0 + r) * SEQ + l0 + c) = h;
    }
}

// ---------------------------------------------------------------------------
// Kernel 3: 1x1 conv.  Per batch b: out[64, 131072] = W[64,128] @ Hcat + bias.
// Channels 0..31 come from X, 32+ from g_hops.  CTA: 64 rows x 64 cols, K=128.
// grid: (2048 col tiles, 8 batches), 256 threads.
// ---------------------------------------------------------------------------
__global__ void conv_kernel(const float* __restrict__ X, const float* __restrict__ W,
                            const float* __restrict__ bias, float* __restrict__ out) {
    const int b = blockIdx.y;
    const int col0 = blockIdx.x * 64;

    __shared__ __align__(16) float smem[10624];    // 42.5 KB
    float* Ws = smem;            // [64][132]
    float* Bs = smem + 8448;     // [32][68]

    const int tid = threadIdx.x;
    const int wid = tid >> 5;
    const int warp_m = wid & 3;          // 4 warps x 16 rows
    const int warp_n = wid >> 2;         // 2 warps x 32 cols

    // Load W (64x128) into smem, tf32-rounded
#pragma unroll
    for (int p = 0; p < 8; p++) {
        int r = p * 8 + (tid >> 5);
        int c = (tid & 31) * 4;
        float4 v = *(const float4*)(W + r * 128 + c);
        v.x = wmma::__float_to_tf32(v.x);
        v.y = wmma::__float_to_tf32(v.y);
        v.z = wmma::__float_to_tf32(v.z);
        v.w = wmma::__float_to_tf32(v.w);
        *(float4*)(Ws + r * 132 + c) = v;
    }

    wmma::fragment<wmma::accumulator, 16, 16, 8, float> acc[2];
    wmma::fill_fragment(acc[0], 0.0f);
    wmma::fill_fragment(acc[1], 0.0f);

    for (int k0 = 0; k0 < 4 * C_IN; k0 += 32) {
        // Load 32 channel rows x 64 cols
#pragma unroll
        for (int p = 0; p < 2; p++) {
            int r = p * 16 + (tid >> 4);
            int c = (tid & 15) * 4;
            int ch = k0 + r;
            const float* rp;
            if (ch < C_IN) {
                rp = X + ((size_t)b * C_IN + ch) * SLICE;
            } else {
                int slot = (ch >> 5) - 1;
                int cc = ch & 31;
                rp = g_hops + (size_t)slot * SLOT + ((size_t)b * C_IN + cc) * SLICE;
            }
            float4 v = *(const float4*)(rp + col0 + c);
            v.x = wmma::__float_to_tf32(v.x);
            v.y = wmma::__float_to_tf32(v.y);
            v.z = wmma::__float_to_tf32(v.z);
            v.w = wmma::__float_to_tf32(v.w);
            *(float4*)(Bs + r * 68 + c) = v;
        }
        __syncthreads();

#pragma unroll
        for (int ks = 0; ks < 32; ks += 8) {
            wmma::fragment<wmma::matrix_a, 16, 16, 8, wmma::precision::tf32, wmma::row_major> a;
            wmma::fragment<wmma::matrix_b, 16, 16, 8, wmma::precision::tf32, wmma::row_major> bb[2];
            wmma::load_matrix_sync(a, Ws + (warp_m * 16) * 132 + k0 + ks, 132);
#pragma unroll
            for (int ni = 0; ni < 2; ni++)
                wmma::load_matrix_sync(bb[ni], Bs + ks * 68 + warp_n * 32 + ni * 16, 68);
#pragma unroll
            for (int ni = 0; ni < 2; ni++)
                wmma::mma_sync(acc[ni], a, bb[ni], acc[ni]);
        }
        __syncthreads();
    }

    // Epilogue: + bias, write out
    float* Cs = smem;  // [64][68] reuse (Ws region, no longer read)
#pragma unroll
    for (int ni = 0; ni < 2; ni++)
        wmma::store_matrix_sync(Cs + (warp_m * 16) * 68 + warp_n * 32 + ni * 16,
                                acc[ni], 68, wmma::mem_row_major);
    __syncthreads();

    const size_t obase = (size_t)b * C_OUT * SLICE;
#pragma unroll
    for (int p = 0; p < 4; p++) {
        int r = p * 16 + (tid >> 4);
        int c = (tid & 15) * 4;
        float bv = bias[r];
        float4 cv = *(const float4*)(Cs + r * 68 + c);
        cv.x += bv; cv.y += bv; cv.z += bv; cv.w += bv;
        *(float4*)(out + obase + (size_t)r * SLICE + col0 + c) = cv;
    }
}

// ---------------------------------------------------------------------------
extern "C" void kernel_launch(void* const* d_in, const int* in_sizes, int n_in,
                              void* d_out, int out_size) {
    const float* X    = (const float*)d_in[0];   // [8,32,512,256]
    const float* A    = (const float*)d_in[1];   // [512,512]
    const float* W    = (const float*)d_in[2];   // [64,128]
    const float* bias = (const float*)d_in[3];   // [64]
    float* out = (float*)d_out;                  // [8,64,512,256]

    norm_kernel<<<N_NODES, 256>>>(A);

    dim3 hop_grid(16, B_SZ * C_IN);
    hop_kernel<<<hop_grid, 256>>>(X, -1, 0);   // H1 from X
    hop_kernel<<<hop_grid, 256>>>(X,  0, 1);   // H2
    hop_kernel<<<hop_grid, 256>>>(X,  1, 2);   // H3

    dim3 conv_grid(SLICE / 64, B_SZ);
    conv_kernel<<<conv_grid, 256>>>(X, W, bias, out);
}

// round 7
// speedup vs baseline: 1.0527x; 1.0527x over previous
#include <cuda_runtime.h>
#include <mma.h>

using namespace nvcuda;

#define N_NODES 512
#define SEQ     256
#define C_IN    32
#define B_SZ    8
#define C_OUT   64
#define GDEP    3
#define BETA    0.05f

#define SLICE   (N_NODES * SEQ)              // 131072 floats per (b,c) slice
#define SLOT    (B_SZ * C_IN * SLICE)        // 33554432 floats per hop slot

// Scratch: normalized adjacency (tf32-rounded), tf32-rounded X, 3 hop buffers.
__device__ float g_An[N_NODES * N_NODES];
__device__ float g_X [SLOT];
__device__ float g_hops[(size_t)GDEP * SLOT];

// ---------------------------------------------------------------------------
// cp.async helpers
// ---------------------------------------------------------------------------
__device__ __forceinline__ unsigned smem_u32(const void* p) {
    return (unsigned)__cvta_generic_to_shared(p);
}
__device__ __forceinline__ void cp16(unsigned dst, const void* src) {
    asm volatile("cp.async.cg.shared.global [%0], [%1], 16;\n" :: "r"(dst), "l"(src));
}
#define CP_COMMIT() asm volatile("cp.async.commit_group;\n")
#define CP_WAIT(n)  asm volatile("cp.async.wait_group %0;\n" :: "n"(n))

__device__ __forceinline__ float tf32r(float x) { return wmma::__float_to_tf32(x); }

// ---------------------------------------------------------------------------
// Kernel 1: A' = row-normalize(A + I), stored RN-rounded to tf32.
// ---------------------------------------------------------------------------
__global__ void norm_kernel(const float* __restrict__ A) {
    int v = blockIdx.x;
    int tid = threadIdx.x;
    __shared__ float red[256];
    float s = 0.0f;
    for (int w = tid; w < N_NODES; w += 256)
        s += A[(size_t)v * N_NODES + w] + (w == v ? 1.0f : 0.0f);
    red[tid] = s;
    __syncthreads();
    for (int off = 128; off > 0; off >>= 1) {
        if (tid < off) red[tid] += red[tid + off];
        __syncthreads();
    }
    float inv = 1.0f / red[0];
    for (int w = tid; w < N_NODES; w += 256) {
        float a = A[(size_t)v * N_NODES + w] + (w == v ? 1.0f : 0.0f);
        g_An[(size_t)v * N_NODES + w] = tf32r(a * inv);
    }
}

// ---------------------------------------------------------------------------
// Kernel 1b: g_X = tf32_rn(X)  (so cp.async'd operands are tf32-exact)
// ---------------------------------------------------------------------------
__global__ void roundx_kernel(const float* __restrict__ X) {
    size_t i = ((size_t)blockIdx.x * 256 + threadIdx.x) * 4;
    float4 v = *(const float4*)(X + i);
    v.x = tf32r(v.x); v.y = tf32r(v.y); v.z = tf32r(v.z); v.w = tf32r(v.w);
    *(float4*)(g_X + i) = v;
}

// ---------------------------------------------------------------------------
// Kernel 2: hop GEMM, cp.async 3-stage pipeline.
// Per (b,c) slice: Hk = A'(512x512) @ Hprev(512x256); Hnext = b*X + (1-b)*Hk.
// CTA tile 128x128, k-step 32, 8 warps (2m x 4n), warp tile 64x32.
// grid: (8 tiles, 256 slices), 256 threads. Dyn smem: 3*(128*36+32*136)*4 B.
// ---------------------------------------------------------------------------
#define HK_AS    4608                    // 128*36 floats
#define HK_BS    4352                    // 32*136 floats
#define HK_STAGE (HK_AS + HK_BS)         // 8960 floats
#define HK_SMEM  (3 * HK_STAGE * 4)      // 107520 bytes

__global__ __launch_bounds__(256, 2) void hop_kernel(int src_slot, int dst_slot) {
    const float* __restrict__ src = (src_slot < 0) ? g_X : (g_hops + (size_t)src_slot * SLOT);
    float* __restrict__ dst = g_hops + (size_t)dst_slot * SLOT;

    const int bc = blockIdx.y;
    const int mt = blockIdx.x & 3;       // 4 row tiles of 128
    const int nt = blockIdx.x >> 2;      // 2 col tiles of 128
    const size_t sbase = (size_t)bc * SLICE;
    const int v0 = mt * 128;
    const int l0 = nt * 128;

    extern __shared__ __align__(16) float sm[];

    const int tid = threadIdx.x;
    const int wid = tid >> 5;
    const int wm = wid & 1;              // 2 warps along rows (64 each)
    const int wn = wid >> 1;             // 4 warps along cols (32 each)

    auto issue = [&](int kk, int s) {
        float* As = sm + s * HK_STAGE;
        float* Bs = As + HK_AS;
        const int k0 = kk * 32;
#pragma unroll
        for (int i = 0; i < 4; i++) {    // A' tile: 128x32
            int id = tid + i * 256;
            int r = id >> 3, c = (id & 7) * 4;
            cp16(smem_u32(As + r * 36 + c), g_An + (size_t)(v0 + r) * N_NODES + k0 + c);
        }
#pragma unroll
        for (int i = 0; i < 4; i++) {    // H tile: 32x128
            int id = tid + i * 256;
            int r = id >> 5, c = (id & 31) * 4;
            cp16(smem_u32(Bs + r * 136 + c), src + sbase + (size_t)(k0 + r) * SEQ + l0 + c);
        }
    };

    wmma::fragment<wmma::accumulator, 16, 16, 8, float> acc[4][2];
#pragma unroll
    for (int i = 0; i < 4; i++)
#pragma unroll
        for (int j = 0; j < 2; j++)
            wmma::fill_fragment(acc[i][j], 0.0f);

    issue(0, 0); CP_COMMIT();
    issue(1, 1); CP_COMMIT();

    for (int i = 0; i < 16; i++) {
        CP_WAIT(1);
        __syncthreads();
        if (i + 2 < 16) issue(i + 2, (i + 2) % 3);
        CP_COMMIT();

        const float* As = sm + (i % 3) * HK_STAGE;
        const float* Bs = As + HK_AS;
#pragma unroll
        for (int ks = 0; ks < 32; ks += 8) {
            wmma::fragment<wmma::matrix_a, 16, 16, 8, wmma::precision::tf32, wmma::row_major> a[4];
            wmma::fragment<wmma::matrix_b, 16, 16, 8, wmma::precision::tf32, wmma::row_major> b[2];
#pragma unroll
            for (int mi = 0; mi < 4; mi++)
                wmma::load_matrix_sync(a[mi], As + (wm * 64 + mi * 16) * 36 + ks, 36);
#pragma unroll
            for (int ni = 0; ni < 2; ni++)
                wmma::load_matrix_sync(b[ni], Bs + ks * 136 + wn * 32 + ni * 16, 136);
#pragma unroll
            for (int mi = 0; mi < 4; mi++)
#pragma unroll
                for (int ni = 0; ni < 2; ni++)
                    wmma::mma_sync(acc[mi][ni], a[mi], b[ni], acc[mi][ni]);
        }
    }

    __syncthreads();
    // Epilogue: Hnext = BETA*X + (1-BETA)*acc, stored RN-rounded to tf32
    float* Cs = sm;  // [128][136] reuse (17408 floats < 3*HK_STAGE)
#pragma unroll
    for (int mi = 0; mi < 4; mi++)
#pragma unroll
        for (int ni = 0; ni < 2; ni++)
            wmma::store_matrix_sync(Cs + (wm * 64 + mi * 16) * 136 + wn * 32 + ni * 16,
                                    acc[mi][ni], 136, wmma::mem_row_major);
    __syncthreads();

#pragma unroll
    for (int p = 0; p < 16; p++) {
        int id = tid + p * 256;
        int r = id >> 5, c = (id & 31) * 4;
        float4 cv = *(const float4*)(Cs + r * 136 + c);
        float4 xv = *(const float4*)(g_X + sbase + (size_t)(v0 + r) * SEQ + l0 + c);
        float4 h;
        h.x = tf32r(BETA * xv.x + (1.0f - BETA) * cv.x);
        h.y = tf32r(BETA * xv.y + (1.0f - BETA) * cv.y);
        h.z = tf32r(BETA * xv.z + (1.0f - BETA) * cv.z);
        h.w = tf32r(BETA * xv.w + (1.0f - BETA) * cv.w);
        *(float4*)(dst + sbase + (size_t)(v0 + r) * SEQ + l0 + c) = h;
    }
}

// ---------------------------------------------------------------------------
// Kernel 3: 1x1 conv, cp.async 2-stage. out[64,131072] = W[64,128]@Hcat + bias.
// CTA 64 rows x 128 cols, K=128, k-step 32. grid (1024, 8), 256 threads.
// Dyn smem: Ws 64x132 + 2 stages of 32x136 = 68608 bytes.
// ---------------------------------------------------------------------------
#define CV_WS    8448                    // 64*132 floats
#define CV_BS    4352                    // 32*136 floats
#define CV_SMEM  ((CV_WS + 2 * CV_BS) * 4)

__global__ __launch_bounds__(256, 2) void conv_kernel(const float* __restrict__ W,
                                                      const float* __restrict__ bias,
                                                      float* __restrict__ out) {
    const int b = blockIdx.y;
    const int col0 = blockIdx.x * 128;

    extern __shared__ __align__(16) float sm[];
    float* Ws = sm;

    const int tid = threadIdx.x;
    const int wid = tid >> 5;
    const int wm = wid & 1;              // 2 warps x 32 rows
    const int wn = wid >> 1;             // 4 warps x 32 cols

    auto issue = [&](int kk, int s) {
        float* Bs = sm + CV_WS + s * CV_BS;
        const int k0 = kk * 32;
#pragma unroll
        for (int i = 0; i < 4; i++) {
            int id = tid + i * 256;
            int r = id >> 5, c = (id & 31) * 4;
            int ch = k0 + r;
            const float* rp = (ch < C_IN)
                ? (g_X + ((size_t)b * C_IN + ch) * SLICE)
                : (g_hops + (size_t)((ch >> 5) - 1) * SLOT + ((size_t)b * C_IN + (ch & 31)) * SLICE);
            cp16(smem_u32(Bs + r * 136 + c), rp + col0 + c);
        }
    };

    issue(0, 0); CP_COMMIT();

    // Load W (64x128) into smem, tf32 RN-rounded (overlaps with cp.async above)
#pragma unroll
    for (int p = 0; p < 8; p++) {
        int id = tid + p * 256;
        int r = id >> 5, c = (id & 31) * 4;
        float4 v = *(const float4*)(W + r * 128 + c);
        v.x = tf32r(v.x); v.y = tf32r(v.y); v.z = tf32r(v.z); v.w = tf32r(v.w);
        *(float4*)(Ws + r * 132 + c) = v;
    }

    wmma::fragment<wmma::accumulator, 16, 16, 8, float> acc[2][2];
#pragma unroll
    for (int i = 0; i < 2; i++)
#pragma unroll
        for (int j = 0; j < 2; j++)
            wmma::fill_fragment(acc[i][j], 0.0f);

    for (int i = 0; i < 4; i++) {
        CP_WAIT(0);
        __syncthreads();
        if (i + 1 < 4) issue(i + 1, (i + 1) & 1);
        CP_COMMIT();

        const float* Bs = sm + CV_WS + (i & 1) * CV_BS;
        const int k0 = i * 32;
#pragma unroll
        for (int ks = 0; ks < 32; ks += 8) {
            wmma::fragment<wmma::matrix_a, 16, 16, 8, wmma::precision::tf32, wmma::row_major> a[2];
            wmma::fragment<wmma::matrix_b, 16, 16, 8, wmma::precision::tf32, wmma::row_major> bb[2];
#pragma unroll
            for (int mi = 0; mi < 2; mi++)
                wmma::load_matrix_sync(a[mi], Ws + (wm * 32 + mi * 16) * 132 + k0 + ks, 132);
#pragma unroll
            for (int ni = 0; ni < 2; ni++)
                wmma::load_matrix_sync(bb[ni], Bs + ks * 136 + wn * 32 + ni * 16, 136);
#pragma unroll
            for (int mi = 0; mi < 2; mi++)
#pragma unroll
                for (int ni = 0; ni < 2; ni++)
                    wmma::mma_sync(acc[mi][ni], a[mi], bb[ni], acc[mi][ni]);
        }
    }

    __syncthreads();
    float* Cs = sm + CV_WS;  // [64][136] = 8704 floats, fits in both stages
#pragma unroll
    for (int mi = 0; mi < 2; mi++)
#pragma unroll
        for (int ni = 0; ni < 2; ni++)
            wmma::store_matrix_sync(Cs + (wm * 32 + mi * 16) * 136 + wn * 32 + ni * 16,
                                    acc[mi][ni], 136, wmma::mem_row_major);
    __syncthreads();

    const size_t obase = (size_t)b * C_OUT * SLICE;
#pragma unroll
    for (int p = 0; p < 8; p++) {
        int id = tid + p * 256;
        int r = id >> 5, c = (id & 31) * 4;
        float bv = __ldg(bias + r);
        float4 cv = *(const float4*)(Cs + r * 136 + c);
        cv.x += bv; cv.y += bv; cv.z += bv; cv.w += bv;
        *(float4*)(out + obase + (size_t)r * SLICE + col0 + c) = cv;
    }
}

// ---------------------------------------------------------------------------
extern "C" void kernel_launch(void* const* d_in, const int* in_sizes, int n_in,
                              void* d_out, int out_size) {
    const float* X    = (const float*)d_in[0];   // [8,32,512,256]
    const float* A    = (const float*)d_in[1];   // [512,512]
    const float* W    = (const float*)d_in[2];   // [64,128]
    const float* bias = (const float*)d_in[3];   // [64]
    float* out = (float*)d_out;                  // [8,64,512,256]

    cudaFuncSetAttribute(hop_kernel,  cudaFuncAttributeMaxDynamicSharedMemorySize, HK_SMEM);
    cudaFuncSetAttribute(conv_kernel, cudaFuncAttributeMaxDynamicSharedMemorySize, CV_SMEM);
    cudaFuncSetAttribute(hop_kernel,  cudaFuncAttributePreferredSharedMemoryCarveout, 100);
    cudaFuncSetAttribute(conv_kernel, cudaFuncAttributePreferredSharedMemoryCarveout, 100);

    norm_kernel<<<N_NODES, 256>>>(A);
    roundx_kernel<<<SLOT / (256 * 4), 256>>>(X);

    dim3 hop_grid(8, B_SZ * C_IN);
    hop_kernel<<<hop_grid, 256, HK_SMEM>>>(-1, 0);   // H1 from X
    hop_kernel<<<hop_grid, 256, HK_SMEM>>>( 0, 1);   // H2
    hop_kernel<<<hop_grid, 256, HK_SMEM>>>( 1, 2);   // H3

    dim3 conv_grid(SLICE / 128, B_SZ);
    conv_kernel<<<conv_grid, 256, CV_SMEM>>>(W, bias, out);
}

// round 9
// speedup vs baseline: 3.0637x; 2.9104x over previous
#include <cuda_runtime.h>
#include <cuda_fp16.h>
#include <mma.h>
#include <cstdint>

using namespace nvcuda;

#define N_NODES 512
#define SEQ     256
#define C_IN    32
#define B_SZ    8
#define C_OUT   64
#define GDEP    3
#define BETA    0.05f

#define SLICE   (N_NODES * SEQ)              // 131072 elems per (b,c) slice
#define SLOT    (B_SZ * C_IN * SLICE)        // 33554432 elems per hop slot

// fp16 operand storage: normalized adjacency, rounded X, hop buffers.
__device__ __half g_An[N_NODES * N_NODES];
__device__ __half g_Xh[SLOT];
__device__ __half g_hops[(size_t)GDEP * SLOT];

// ---------------------------------------------------------------------------
// cp.async helpers
// ---------------------------------------------------------------------------
__device__ __forceinline__ unsigned smem_u32(const void* p) {
    return (unsigned)__cvta_generic_to_shared(p);
}
__device__ __forceinline__ void cp16(unsigned dst, const void* src) {
    asm volatile("cp.async.cg.shared.global [%0], [%1], 16;\n" :: "r"(dst), "l"(src));
}
#define CP_COMMIT() asm volatile("cp.async.commit_group;\n")
#define CP_WAIT(n)  asm volatile("cp.async.wait_group %0;\n" :: "n"(n))

// ---------------------------------------------------------------------------
// Kernel 1: A' = row-normalize(A + I), stored fp16.
// ---------------------------------------------------------------------------
__global__ void norm_kernel(const float* __restrict__ A) {
    int v = blockIdx.x;
    int tid = threadIdx.x;
    __shared__ float red[256];
    float s = 0.0f;
    for (int w = tid; w < N_NODES; w += 256)
        s += A[(size_t)v * N_NODES + w] + (w == v ? 1.0f : 0.0f);
    red[tid] = s;
    __syncthreads();
    for (int off = 128; off > 0; off >>= 1) {
        if (tid < off) red[tid] += red[tid + off];
        __syncthreads();
    }
    float inv = 1.0f / red[0];
    for (int w = tid; w < N_NODES; w += 256) {
        float a = A[(size_t)v * N_NODES + w] + (w == v ? 1.0f : 0.0f);
        g_An[(size_t)v * N_NODES + w] = __float2half_rn(a * inv);
    }
}

// ---------------------------------------------------------------------------
// Kernel 1b: g_Xh = fp16(X). Each thread converts 8 elements.
// ---------------------------------------------------------------------------
__global__ void xprep_kernel(const float* __restrict__ X) {
    size_t i = ((size_t)blockIdx.x * 256 + threadIdx.x) * 8;
    float4 v0 = *(const float4*)(X + i);
    float4 v1 = *(const float4*)(X + i + 4);
    __half2 h[4];
    h[0] = __floats2half2_rn(v0.x, v0.y);
    h[1] = __floats2half2_rn(v0.z, v0.w);
    h[2] = __floats2half2_rn(v1.x, v1.y);
    h[3] = __floats2half2_rn(v1.z, v1.w);
    *(uint4*)(g_Xh + i) = *(uint4*)h;
}

// ---------------------------------------------------------------------------
// Kernel 2: hop GEMM, fp16 HMMA, cp.async 3-stage pipeline.
// Per (b,c) slice: Hk = A'(512x512) @ Hprev(512x256); Hnext = b*X + (1-b)*Hk.
// CTA tile 128x128, k-chunk 32 (2 x k16), 8 warps (2m x 4n), warp tile 64x32.
// grid: (8, 256), 256 threads.
// ---------------------------------------------------------------------------
#define HK_A     5120                    // 128*40 halfs (80B rows)
#define HK_B     4352                    // 32*136 halfs (272B rows)
#define HK_STAGE (HK_A + HK_B)           // 9472 halfs = 18944 B
#define HK_SMEM  67584                   // max(3*stage=56832, Cs 128*132*4=67584)

__global__ __launch_bounds__(256, 2) void hop_kernel(const __half* __restrict__ src,
                                                     __half* __restrict__ dst) {
    const int bc = blockIdx.y;
    const int mt = blockIdx.x & 3;       // 4 row tiles of 128
    const int nt = blockIdx.x >> 2;      // 2 col tiles of 128
    const size_t sbase = (size_t)bc * SLICE;
    const int v0 = mt * 128;
    const int l0 = nt * 128;

    extern __shared__ __align__(16) char smc[];
    __half* smh = (__half*)smc;

    const int tid = threadIdx.x;
    const int wid = tid >> 5;
    const int wm = wid & 1;              // 2 warps along rows (64 each)
    const int wn = wid >> 1;             // 4 warps along cols (32 each)

    auto issue = [&](int kk, int s) {
        __half* As = smh + s * HK_STAGE;
        __half* Bs = As + HK_A;
        const int k0 = kk * 32;
#pragma unroll
        for (int i = 0; i < 2; i++) {    // A' tile 128x32 halfs: 512 granules
            int g = tid + i * 256;
            int r = g >> 2, c = g & 3;
            cp16(smem_u32(As + r * 40 + c * 8), g_An + (size_t)(v0 + r) * N_NODES + k0 + c * 8);
        }
#pragma unroll
        for (int i = 0; i < 2; i++) {    // H tile 32x128 halfs: 512 granules
            int g = tid + i * 256;
            int r = g >> 4, c = g & 15;
            cp16(smem_u32(Bs + r * 136 + c * 8), src + sbase + (size_t)(k0 + r) * SEQ + l0 + c * 8);
        }
    };

    wmma::fragment<wmma::accumulator, 16, 16, 16, float> acc[4][2];
#pragma unroll
    for (int i = 0; i < 4; i++)
#pragma unroll
        for (int j = 0; j < 2; j++)
            wmma::fill_fragment(acc[i][j], 0.0f);

    issue(0, 0); CP_COMMIT();
    issue(1, 1); CP_COMMIT();

    for (int i = 0; i < 16; i++) {
        CP_WAIT(1);
        __syncthreads();
        if (i + 2 < 16) issue(i + 2, (i + 2) % 3);
        CP_COMMIT();

        const __half* As = smh + (i % 3) * HK_STAGE;
        const __half* Bs = As + HK_A;
#pragma unroll
        for (int ks = 0; ks < 2; ks++) {
            wmma::fragment<wmma::matrix_a, 16, 16, 16, __half, wmma::row_major> a[4];
            wmma::fragment<wmma::matrix_b, 16, 16, 16, __half, wmma::row_major> b[2];
#pragma unroll
            for (int mi = 0; mi < 4; mi++)
                wmma::load_matrix_sync(a[mi], As + (wm * 64 + mi * 16) * 40 + ks * 16, 40);
#pragma unroll
            for (int ni = 0; ni < 2; ni++)
                wmma::load_matrix_sync(b[ni], Bs + (ks * 16) * 136 + wn * 32 + ni * 16, 136);
#pragma unroll
            for (int mi = 0; mi < 4; mi++)
#pragma unroll
                for (int ni = 0; ni < 2; ni++)
                    wmma::mma_sync(acc[mi][ni], a[mi], b[ni], acc[mi][ni]);
        }
    }

    __syncthreads();
    // Epilogue: Hnext = BETA*X + (1-BETA)*acc -> fp16
    float* Cs = (float*)smc;  // [128][132]
#pragma unroll
    for (int mi = 0; mi < 4; mi++)
#pragma unroll
        for (int ni = 0; ni < 2; ni++)
            wmma::store_matrix_sync(Cs + (wm * 64 + mi * 16) * 132 + wn * 32 + ni * 16,
                                    acc[mi][ni], 132, wmma::mem_row_major);
    __syncthreads();

#pragma unroll
    for (int p = 0; p < 8; p++) {        // 128x128 elems, 8-elem groups
        int id = tid + p * 256;
        int r = id >> 4, c = (id & 15) * 8;
        float4 c0 = *(const float4*)(Cs + r * 132 + c);
        float4 c1 = *(const float4*)(Cs + r * 132 + c + 4);
        uint4 xr = *(const uint4*)(g_Xh + sbase + (size_t)(v0 + r) * SEQ + l0 + c);
        __half2* xh = (__half2*)&xr;
        float2 x0 = __half22float2(xh[0]);
        float2 x1 = __half22float2(xh[1]);
        float2 x2 = __half22float2(xh[2]);
        float2 x3 = __half22float2(xh[3]);
        __half2 o[4];
        o[0] = __floats2half2_rn(BETA * x0.x + (1.0f - BETA) * c0.x,
                                 BETA * x0.y + (1.0f - BETA) * c0.y);
        o[1] = __floats2half2_rn(BETA * x1.x + (1.0f - BETA) * c0.z,
                                 BETA * x1.y + (1.0f - BETA) * c0.w);
        o[2] = __floats2half2_rn(BETA * x2.x + (1.0f - BETA) * c1.x,
                                 BETA * x2.y + (1.0f - BETA) * c1.y);
        o[3] = __floats2half2_rn(BETA * x3.x + (1.0f - BETA) * c1.z,
                                 BETA * x3.y + (1.0f - BETA) * c1.w);
        *(uint4*)(dst + sbase + (size_t)(v0 + r) * SEQ + l0 + c) = *(uint4*)o;
    }
}

// ---------------------------------------------------------------------------
// Kernel 3: 1x1 conv, fp16 HMMA, cp.async 2-stage.
// out[64,131072] = W[64,128] @ Hcat + bias. CTA 64 x 128, k-chunk 32.
// grid (1024, 8), 256 threads.
// ---------------------------------------------------------------------------
#define CV_WS    8704                    // 64*136 halfs = 17408 B
#define CV_BS    4352                    // 32*136 halfs =  8704 B
#define CV_SMEM  ((CV_WS + 2 * CV_BS) * 2)   // 34816 B (Cs 64*132*4=33792 fits)

__global__ __launch_bounds__(256, 2) void conv_kernel(const float* __restrict__ W,
                                                      const float* __restrict__ bias,
                                                      float* __restrict__ out) {
    const int b = blockIdx.y;
    const int col0 = blockIdx.x * 128;

    extern __shared__ __align__(16) char smc[];
    __half* Ws = (__half*)smc;

    const int tid = threadIdx.x;
    const int wid = tid >> 5;
    const int wm = wid & 1;              // 2 warps x 32 rows
    const int wn = wid >> 1;             // 4 warps x 32 cols

    auto issue = [&](int kk, int s) {
        __half* Bs = Ws + CV_WS + s * CV_BS;
        const int k0 = kk * 32;
#pragma unroll
        for (int i = 0; i < 2; i++) {
            int g = tid + i * 256;
            int r = g >> 4, c = g & 15;
            int ch = k0 + r;
            const __half* rp = (ch < C_IN)
                ? (g_Xh + ((size_t)b * C_IN + ch) * SLICE)
                : (g_hops + (size_t)((ch >> 5) - 1) * SLOT + ((size_t)b * C_IN + (ch & 31)) * SLICE);
            cp16(smem_u32(Bs + r * 136 + c * 8), rp + col0 + c * 8);
        }
    };

    issue(0, 0); CP_COMMIT();

    // Load W (64x128) -> fp16 smem
#pragma unroll
    for (int p = 0; p < 4; p++) {
        int id = tid + p * 256;
        int r = id >> 4, c = (id & 15) * 8;
        float4 v0 = *(const float4*)(W + r * 128 + c);
        float4 v1 = *(const float4*)(W + r * 128 + c + 4);
        __half2 h[4];
        h[0] = __floats2half2_rn(v0.x, v0.y);
        h[1] = __floats2half2_rn(v0.z, v0.w);
        h[2] = __floats2half2_rn(v1.x, v1.y);
        h[3] = __floats2half2_rn(v1.z, v1.w);
        *(uint4*)(Ws + r * 136 + c) = *(uint4*)h;
    }

    wmma::fragment<wmma::accumulator, 16, 16, 16, float> acc[2][2];
#pragma unroll
    for (int i = 0; i < 2; i++)
#pragma unroll
        for (int j = 0; j < 2; j++)
            wmma::fill_fragment(acc[i][j], 0.0f);

    for (int i = 0; i < 4; i++) {
        CP_WAIT(0);
        __syncthreads();
        if (i + 1 < 4) issue(i + 1, (i + 1) & 1);
        CP_COMMIT();

        const __half* Bs = Ws + CV_WS + (i & 1) * CV_BS;
        const int k0 = i * 32;
#pragma unroll
        for (int ks = 0; ks < 2; ks++) {
            wmma::fragment<wmma::matrix_a, 16, 16, 16, __half, wmma::row_major> a[2];
            wmma::fragment<wmma::matrix_b, 16, 16, 16, __half, wmma::row_major> bb[2];
#pragma unroll
            for (int mi = 0; mi < 2; mi++)
                wmma::load_matrix_sync(a[mi], Ws + (wm * 32 + mi * 16) * 136 + k0 + ks * 16, 136);
#pragma unroll
            for (int ni = 0; ni < 2; ni++)
                wmma::load_matrix_sync(bb[ni], Bs + (ks * 16) * 136 + wn * 32 + ni * 16, 136);
#pragma unroll
            for (int mi = 0; mi < 2; mi++)
#pragma unroll
                for (int ni = 0; ni < 2; ni++)
                    wmma::mma_sync(acc[mi][ni], a[mi], bb[ni], acc[mi][ni]);
        }
    }

    __syncthreads();
    float* Cs = (float*)smc;  // [64][132] = 33792 B, overlays Ws+Bs (done)
#pragma unroll
    for (int mi = 0; mi < 2; mi++)
#pragma unroll
        for (int ni = 0; ni < 2; ni++)
            wmma::store_matrix_sync(Cs + (wm * 32 + mi * 16) * 132 + wn * 32 + ni * 16,
                                    acc[mi][ni], 132, wmma::mem_row_major);
    __syncthreads();

    const size_t obase = (size_t)b * C_OUT * SLICE;
#pragma unroll
    for (int p = 0; p < 8; p++) {
        int id = tid + p * 256;
        int r = id >> 5, c = (id & 31) * 4;
        float bv = __ldg(bias + r);
        float4 cv = *(const float4*)(Cs + r * 132 + c);
        cv.x += bv; cv.y += bv; cv.z += bv; cv.w += bv;
        *(float4*)(out + obase + (size_t)r * SLICE + col0 + c) = cv;
    }
}

// ---------------------------------------------------------------------------
extern "C" void kernel_launch(void* const* d_in, const int* in_sizes, int n_in,
                              void* d_out, int out_size) {
    const float* X    = (const float*)d_in[0];   // [8,32,512,256]
    const float* A    = (const float*)d_in[1];   // [512,512]
    const float* W    = (const float*)d_in[2];   // [64,128]
    const float* bias = (const float*)d_in[3];   // [64]
    float* out = (float*)d_out;                  // [8,64,512,256]

    cudaFuncSetAttribute(hop_kernel,  cudaFuncAttributeMaxDynamicSharedMemorySize, HK_SMEM);
    cudaFuncSetAttribute(conv_kernel, cudaFuncAttributeMaxDynamicSharedMemorySize, CV_SMEM);
    cudaFuncSetAttribute(hop_kernel,  cudaFuncAttributePreferredSharedMemoryCarveout, 100);
    cudaFuncSetAttribute(conv_kernel, cudaFuncAttributePreferredSharedMemoryCarveout, 100);

    norm_kernel<<<N_NODES, 256>>>(A);
    xprep_kernel<<<SLOT / (256 * 8), 256>>>(X);

    __half *hops, *xh;
    cudaGetSymbolAddress((void**)&hops, g_hops);
    cudaGetSymbolAddress((void**)&xh,   g_Xh);

    dim3 hg(8, B_SZ * C_IN);
    hop_kernel<<<hg, 256, HK_SMEM>>>(xh,              hops);             // H1
    hop_kernel<<<hg, 256, HK_SMEM>>>(hops,            hops + 1 * SLOT);  // H2
    hop_kernel<<<hg, 256, HK_SMEM>>>(hops + 1 * SLOT, hops + 2 * SLOT);  // H3

    dim3 cg(SLICE / 128, B_SZ);
    conv_kernel<<<cg, 256, CV_SMEM>>>(W, bias, out);
}